// round 3
// baseline (speedup 1.0000x reference)
#include <cuda_runtime.h>
#include <cstdint>

typedef unsigned long long ull;

#define NSEQ 480
#define TLEN 200
#define CH   64
#define HID  128
#define G4   512
#define NROW (NSEQ * TLEN)   // 96000

// ---------------- device scratch (no allocs allowed) ----------------
__device__ float g_xf[NROW * CH];      // [t*480+seq][c]
__device__ float g_xg[NROW * G4];      // [t*480+seq][g]
__device__ float g_Wp[HID * HID * 4];  // [k][r][{i,f,g,o}]
__device__ float g_Wiht[CH * G4];      // [c][g]
__device__ float g_bias[G4];

// ---------------- f32x2 helpers ----------------
__device__ __forceinline__ ull pk2(float lo, float hi) {
    ull r; asm("mov.b64 %0, {%1, %2};" : "=l"(r) : "f"(lo), "f"(hi)); return r;
}
__device__ __forceinline__ void upk2(ull v, float& lo, float& hi) {
    asm("mov.b64 {%0, %1}, %2;" : "=f"(lo), "=f"(hi) : "l"(v));
}
__device__ __forceinline__ void fma2(ull& a, ull b, ull c) {
    asm("fma.rn.f32x2 %0, %1, %2, %0;" : "+l"(a) : "l"(b), "l"(c));
}
__device__ __forceinline__ void add2(ull& a, ull b) {
    asm("add.rn.f32x2 %0, %0, %1;" : "+l"(a) : "l"(b));
}

// ---------------- prep ----------------
__global__ void __launch_bounds__(256) prep_kernel(
    const float* __restrict__ Wih, const float* __restrict__ Whh,
    const float* __restrict__ bih, const float* __restrict__ bhh)
{
    int idx = blockIdx.x * 256 + threadIdx.x;
    if (idx < HID * HID * 4) {
        int qg = idx & 3, r = (idx >> 2) & 127, k = idx >> 9;
        g_Wp[idx] = Whh[(qg * 128 + r) * 128 + k];
    }
    if (idx < CH * G4) {
        int c = idx >> 9, g = idx & 511;
        g_Wiht[idx] = Wih[g * 64 + c];
    }
    if (idx < G4) g_bias[idx] = bih[idx] + bhh[idx];
}

// ---------------- transpose x: (B,C,T,P) -> xf[t*480 + b*30+p][c] ----------------
__global__ void __launch_bounds__(256) transp_kernel(const float* __restrict__ x)
{
    __shared__ float tile[64 * 30];
    int t = blockIdx.x, b = blockIdx.y;
    for (int idx = threadIdx.x; idx < 64 * 30; idx += 256) {
        int c = idx / 30, p = idx - c * 30;
        tile[idx] = x[(b * 64 + c) * 6000 + t * 30 + p];
    }
    __syncthreads();
    for (int idx = threadIdx.x; idx < 64 * 30; idx += 256) {
        int p = idx >> 6, c = idx & 63;
        g_xf[(t * NSEQ + b * 30 + p) * 64 + c] = tile[c * 30 + p];
    }
}

// ---------------- xg GEMM: 128x128 tile, 8x8 microtile ----------------
// As: [64][132] floats (pad), Bs: [64][128]
#define AS(k, m) As[(k) * 132 + (m)]
#define BS(k, n) Bs[(k) * 128 + (n)]
#define GEMM_SMEM (64 * 132 * 4 + 64 * 128 * 4)

__global__ void __launch_bounds__(256, 2) gemm_kernel()
{
    extern __shared__ float As[];           // then Bs
    float* Bs = As + 64 * 132;
    int tid = threadIdx.x;
    int row0 = blockIdx.x * 128, col0 = blockIdx.y * 128;

    // load A (128 rows x 64 k), store transposed [k][m]
    for (int i = tid; i < 2048; i += 256) {
        int m = i >> 4, k4 = i & 15;
        float4 v = *(const float4*)&g_xf[(row0 + m) * 64 + k4 * 4];
        AS(k4 * 4 + 0, m) = v.x;
        AS(k4 * 4 + 1, m) = v.y;
        AS(k4 * 4 + 2, m) = v.z;
        AS(k4 * 4 + 3, m) = v.w;
    }
    // load B (64 k x 128 n)
    for (int i = tid; i < 2048; i += 256) {
        int k = i >> 5, n4 = i & 31;
        *(float4*)&BS(k, n4 * 4) = *(const float4*)&g_Wiht[k * 512 + col0 + n4 * 4];
    }
    __syncthreads();

    int tm = tid & 15, tn = tid >> 4;
    int m0 = tm * 8, n0 = tn * 8;
    ull acc[8][4];
#pragma unroll
    for (int i = 0; i < 8; i++)
#pragma unroll
        for (int j = 0; j < 4; j++) acc[i][j] = 0;

#pragma unroll 8
    for (int k = 0; k < 64; k++) {
        float4 a0 = *(const float4*)&AS(k, m0);
        float4 a1 = *(const float4*)&AS(k, m0 + 4);
        longlong2 bv0 = *(const longlong2*)&BS(k, n0);
        longlong2 bv1 = *(const longlong2*)&BS(k, n0 + 4);
        ull b[4] = {(ull)bv0.x, (ull)bv0.y, (ull)bv1.x, (ull)bv1.y};
        float am[8] = {a0.x, a0.y, a0.z, a0.w, a1.x, a1.y, a1.z, a1.w};
#pragma unroll
        for (int i = 0; i < 8; i++) {
            ull ad = pk2(am[i], am[i]);
            fma2(acc[i][0], b[0], ad);
            fma2(acc[i][1], b[1], ad);
            fma2(acc[i][2], b[2], ad);
            fma2(acc[i][3], b[3], ad);
        }
    }

    float4 bi0 = *(const float4*)&g_bias[col0 + n0];
    float4 bi1 = *(const float4*)&g_bias[col0 + n0 + 4];
    float bn[8] = {bi0.x, bi0.y, bi0.z, bi0.w, bi1.x, bi1.y, bi1.z, bi1.w};
#pragma unroll
    for (int i = 0; i < 8; i++) {
        float v[8];
        upk2(acc[i][0], v[0], v[1]); upk2(acc[i][1], v[2], v[3]);
        upk2(acc[i][2], v[4], v[5]); upk2(acc[i][3], v[6], v[7]);
        float* dst = &g_xg[(size_t)(row0 + m0 + i) * 512 + col0 + n0];
        float4 o0 = make_float4(v[0] + bn[0], v[1] + bn[1], v[2] + bn[2], v[3] + bn[3]);
        float4 o1 = make_float4(v[4] + bn[4], v[5] + bn[5], v[6] + bn[6], v[7] + bn[7]);
        *(float4*)dst = o0;
        *(float4*)(dst + 4) = o1;
    }
}

// ---------------- persistent LSTM + FC ----------------
#define LS_WS   0                        // 64*128 longlong2 (128 KB)
#define LS_XB   (128 * 1024)             // 2*512 float4 (16 KB)
#define LS_PIF  (LS_XB + 16384)          // 12*128 ull (12 KB)
#define LS_PGO  (LS_PIF + 12288)         // 12*128 ull (12 KB)
#define LS_HD   (LS_PGO + 12288)         // 512 ull (4 KB): (h,h) pairs [k][s]
#define LS_TOTAL (LS_HD + 4096)          // 176128 B

__global__ void __launch_bounds__(512, 1) lstm_kernel(
    const float* __restrict__ Wfc, const float* __restrict__ bfc,
    float* __restrict__ out)
{
    extern __shared__ char smem[];
    longlong2* Ws2 = (longlong2*)(smem + LS_WS);
    float4*    xb4 = (float4*)(smem + LS_XB);
    ull*       pIF = (ull*)(smem + LS_PIF);
    ull*       pGO = (ull*)(smem + LS_PGO);
    ull*       hd  = (ull*)(smem + LS_HD);

    int tid = threadIdx.x;
    int r = tid & 127, q = tid >> 7;
    int s0 = blockIdx.x * 4;

    // seq rotation: accumulator j handles seq (q+j)&3 -> own seq (j=0) is q
    int sq1 = (q + 1) & 3, sq2 = (q + 2) & 3, sq3 = (q + 3) & 3;

    // register half of W_hh: k in [32q, 32q+16)
    ull WIF[16], WGO[16];
    const longlong2* Wp2 = (const longlong2*)g_Wp;
#pragma unroll
    for (int kk = 0; kk < 16; kk++) {
        longlong2 v = Wp2[(32 * q + kk) * 128 + r];
        WIF[kk] = (ull)v.x; WGO[kk] = (ull)v.y;
    }
    // smem half: k in [32q+16, 32q+32)
    for (int idx = tid; idx < 64 * 128; idx += 512) {
        int kidx = idx >> 7, rr = idx & 127;
        int qq = kidx >> 4, kk = (kidx & 15) + 16;
        Ws2[idx] = Wp2[(32 * qq + kk) * 128 + rr];
    }

    hd[tid] = 0ull;
    const float4* xg4 = (const float4*)g_xg;
    xb4[tid] = xg4[(size_t)s0 * 128 + tid];   // t=0 -> buffer 0

    float cst = 0.f;   // c-state for (row r, seq q)
    __syncthreads();

    // reduce-phase source slots (uniform per warp)
    int ofA = (sq1 * 3 + 2) * 128 + r;
    int ofB = (sq2 * 3 + 1) * 128 + r;
    int ofC = (sq3 * 3 + 0) * 128 + r;

#pragma unroll 1
    for (int t = 0; t < TLEN; t++) {
        float4 nx = make_float4(0.f, 0.f, 0.f, 0.f);
        if (t + 1 < TLEN) nx = xg4[((size_t)(t + 1) * NSEQ + s0) * 128 + tid];

        ull aIF0 = 0, aIF1 = 0, aIF2 = 0, aIF3 = 0;
        ull aGO0 = 0, aGO1 = 0, aGO2 = 0, aGO3 = 0;

#pragma unroll
        for (int kk = 0; kk < 16; kk++) {            // register-W half
            int kb = (32 * q + kk) * 4;
            ull h0 = hd[kb + q];
            ull h1 = hd[kb + sq1];
            ull h2 = hd[kb + sq2];
            ull h3 = hd[kb + sq3];
            fma2(aIF0, WIF[kk], h0); fma2(aGO0, WGO[kk], h0);
            fma2(aIF1, WIF[kk], h1); fma2(aGO1, WGO[kk], h1);
            fma2(aIF2, WIF[kk], h2); fma2(aGO2, WGO[kk], h2);
            fma2(aIF3, WIF[kk], h3); fma2(aGO3, WGO[kk], h3);
        }
#pragma unroll
        for (int kk = 0; kk < 16; kk++) {            // smem-W half
            longlong2 wv = Ws2[(q * 16 + kk) * 128 + r];
            ull wIF = (ull)wv.x, wGO = (ull)wv.y;
            int kb = (32 * q + 16 + kk) * 4;
            ull h0 = hd[kb + q];
            ull h1 = hd[kb + sq1];
            ull h2 = hd[kb + sq2];
            ull h3 = hd[kb + sq3];
            fma2(aIF0, wIF, h0); fma2(aGO0, wGO, h0);
            fma2(aIF1, wIF, h1); fma2(aGO1, wGO, h1);
            fma2(aIF2, wIF, h2); fma2(aGO2, wGO, h2);
            fma2(aIF3, wIF, h3); fma2(aGO3, wGO, h3);
        }

        // store partials for the 3 non-owned seqs: slot (q*3 + (j-1))
        pIF[(q * 3 + 0) * 128 + r] = aIF1;  pGO[(q * 3 + 0) * 128 + r] = aGO1;
        pIF[(q * 3 + 1) * 128 + r] = aIF2;  pGO[(q * 3 + 1) * 128 + r] = aGO2;
        pIF[(q * 3 + 2) * 128 + r] = aIF3;  pGO[(q * 3 + 2) * 128 + r] = aGO3;
        if (t + 1 < TLEN) xb4[((t + 1) & 1) * 512 + tid] = nx;
        __syncthreads();

        // reduce (this thread owns row r, seq q; own partial = aIF0/aGO0)
        ull sIF = aIF0, sGO = aGO0;
        add2(sIF, pIF[ofA]); add2(sGO, pGO[ofA]);
        add2(sIF, pIF[ofB]); add2(sGO, pGO[ofB]);
        add2(sIF, pIF[ofC]); add2(sGO, pGO[ofC]);

        float gi, gf, gg, go;
        upk2(sIF, gi, gf); upk2(sGO, gg, go);
        const float* xb = (const float*)&xb4[(t & 1) * 512];
        gi += xb[q * 512 + r];
        gf += xb[q * 512 + 128 + r];
        gg += xb[q * 512 + 256 + r];
        go += xb[q * 512 + 384 + r];

        float i_ = __fdividef(1.f, 1.f + __expf(-gi));
        float f_ = __fdividef(1.f, 1.f + __expf(-gf));
        float o_ = __fdividef(1.f, 1.f + __expf(-go));
        float eg = __expf(-2.f * fabsf(gg));
        float g_ = copysignf(__fdividef(1.f - eg, 1.f + eg), gg);

        cst = f_ * cst + i_ * g_;
        float ec = __expf(-2.f * fabsf(cst));
        float th = copysignf(__fdividef(1.f - ec, 1.f + ec), cst);
        float hv = o_ * th;
        hd[r * 4 + q] = pk2(hv, hv);
        __syncthreads();
    }

    // ---- FC epilogue (reuse Ws2 region for transposed W_fc) ----
    float* wfs = (float*)(smem + LS_WS);
    for (int idx = tid; idx < CH * HID; idx += 512) {
        int c = idx >> 7, j = idx & 127;
        wfs[j * 64 + c] = Wfc[idx];
    }
    __syncthreads();
    if (tid < 256) {
        int c = tid & 63, s = tid >> 6;
        float acc = bfc[c];
#pragma unroll 8
        for (int j = 0; j < HID; j++) {
            float hj, dummy;
            upk2(hd[j * 4 + s], hj, dummy);
            acc += hj * wfs[j * 64 + c];
        }
        out[(s0 + s) * 64 + c] = acc;
    }
}

// ---------------- launch ----------------
extern "C" void kernel_launch(void* const* d_in, const int* in_sizes, int n_in,
                              void* d_out, int out_size)
{
    const float* x   = (const float*)d_in[0];
    const float* Wih = (const float*)d_in[1];
    const float* Whh = (const float*)d_in[2];
    const float* bih = (const float*)d_in[3];
    const float* bhh = (const float*)d_in[4];
    const float* Wfc = (const float*)d_in[5];
    const float* bfc = (const float*)d_in[6];
    float* out = (float*)d_out;

    cudaFuncSetAttribute(gemm_kernel, cudaFuncAttributeMaxDynamicSharedMemorySize, GEMM_SMEM);
    cudaFuncSetAttribute(lstm_kernel, cudaFuncAttributeMaxDynamicSharedMemorySize, LS_TOTAL);

    prep_kernel<<<256, 256>>>(Wih, Whh, bih, bhh);
    transp_kernel<<<dim3(TLEN, 16), 256>>>(x);
    gemm_kernel<<<dim3(NROW / 128, G4 / 128), 256, GEMM_SMEM>>>();
    lstm_kernel<<<120, 512, LS_TOTAL>>>(Wfc, bfc, out);
}

// round 4
// speedup vs baseline: 1.1716x; 1.1716x over previous
#include <cuda_runtime.h>
#include <cstdint>

typedef unsigned long long ull;

#define NSEQ 480
#define TLEN 200
#define CH   64
#define HID  128
#define G4   512
#define NROW (NSEQ * TLEN)   // 96000

// ---------------- device scratch (no allocs allowed) ----------------
__device__ float g_xf[NROW * CH];      // [t*480+seq][c]
__device__ float g_xg[NROW * G4];      // [t*480+seq][g]
__device__ float g_Wp[HID * HID * 4];  // [k][r][{i,f,g,o}]
__device__ float g_Wiht[CH * G4];      // [c][g]
__device__ float g_bias[G4];

// ---------------- f32x2 helpers ----------------
__device__ __forceinline__ ull pk2(float lo, float hi) {
    ull r; asm("mov.b64 %0, {%1, %2};" : "=l"(r) : "f"(lo), "f"(hi)); return r;
}
__device__ __forceinline__ void upk2(ull v, float& lo, float& hi) {
    asm("mov.b64 {%0, %1}, %2;" : "=f"(lo), "=f"(hi) : "l"(v));
}
__device__ __forceinline__ void fma2(ull& a, ull b, ull c) {
    asm("fma.rn.f32x2 %0, %1, %2, %0;" : "+l"(a) : "l"(b), "l"(c));
}
__device__ __forceinline__ void add2(ull& a, ull b) {
    asm("add.rn.f32x2 %0, %0, %1;" : "+l"(a) : "l"(b));
}
__device__ __forceinline__ float tanh_t(float x) {
    float t; asm("tanh.approx.f32 %0, %1;" : "=f"(t) : "f"(x)); return t;
}

// ---------------- prep ----------------
__global__ void __launch_bounds__(256) prep_kernel(
    const float* __restrict__ Wih, const float* __restrict__ Whh,
    const float* __restrict__ bih, const float* __restrict__ bhh)
{
    int idx = blockIdx.x * 256 + threadIdx.x;
    if (idx < HID * HID * 4) {
        int qg = idx & 3, r = (idx >> 2) & 127, k = idx >> 9;
        g_Wp[idx] = Whh[(qg * 128 + r) * 128 + k];
    }
    if (idx < CH * G4) {
        int c = idx >> 9, g = idx & 511;
        g_Wiht[idx] = Wih[g * 64 + c];
    }
    if (idx < G4) g_bias[idx] = bih[idx] + bhh[idx];
}

// ---------------- transpose x: (B,C,T,P) -> xf[t*480 + b*30+p][c] ----------------
__global__ void __launch_bounds__(256) transp_kernel(const float* __restrict__ x)
{
    __shared__ float tile[64 * 30];
    int t = blockIdx.x, b = blockIdx.y;
    for (int idx = threadIdx.x; idx < 64 * 30; idx += 256) {
        int c = idx / 30, p = idx - c * 30;
        tile[idx] = x[(b * 64 + c) * 6000 + t * 30 + p];
    }
    __syncthreads();
    for (int idx = threadIdx.x; idx < 64 * 30; idx += 256) {
        int p = idx >> 6, c = idx & 63;
        g_xf[(t * NSEQ + b * 30 + p) * 64 + c] = tile[c * 30 + p];
    }
}

// ---------------- xg GEMM: 128x128 tile, 8x8 microtile ----------------
#define AS(k, m) As[(k) * 132 + (m)]
#define BS(k, n) Bs[(k) * 128 + (n)]
#define GEMM_SMEM (64 * 132 * 4 + 64 * 128 * 4)

__global__ void __launch_bounds__(256, 2) gemm_kernel()
{
    extern __shared__ float As[];           // then Bs
    float* Bs = As + 64 * 132;
    int tid = threadIdx.x;
    int row0 = blockIdx.x * 128, col0 = blockIdx.y * 128;

    for (int i = tid; i < 2048; i += 256) {
        int m = i >> 4, k4 = i & 15;
        float4 v = *(const float4*)&g_xf[(row0 + m) * 64 + k4 * 4];
        AS(k4 * 4 + 0, m) = v.x;
        AS(k4 * 4 + 1, m) = v.y;
        AS(k4 * 4 + 2, m) = v.z;
        AS(k4 * 4 + 3, m) = v.w;
    }
    for (int i = tid; i < 2048; i += 256) {
        int k = i >> 5, n4 = i & 31;
        *(float4*)&BS(k, n4 * 4) = *(const float4*)&g_Wiht[k * 512 + col0 + n4 * 4];
    }
    __syncthreads();

    int tm = tid & 15, tn = tid >> 4;
    int m0 = tm * 8, n0 = tn * 8;
    ull acc[8][4];
#pragma unroll
    for (int i = 0; i < 8; i++)
#pragma unroll
        for (int j = 0; j < 4; j++) acc[i][j] = 0;

#pragma unroll 8
    for (int k = 0; k < 64; k++) {
        float4 a0 = *(const float4*)&AS(k, m0);
        float4 a1 = *(const float4*)&AS(k, m0 + 4);
        longlong2 bv0 = *(const longlong2*)&BS(k, n0);
        longlong2 bv1 = *(const longlong2*)&BS(k, n0 + 4);
        ull b[4] = {(ull)bv0.x, (ull)bv0.y, (ull)bv1.x, (ull)bv1.y};
        float am[8] = {a0.x, a0.y, a0.z, a0.w, a1.x, a1.y, a1.z, a1.w};
#pragma unroll
        for (int i = 0; i < 8; i++) {
            ull ad = pk2(am[i], am[i]);
            fma2(acc[i][0], b[0], ad);
            fma2(acc[i][1], b[1], ad);
            fma2(acc[i][2], b[2], ad);
            fma2(acc[i][3], b[3], ad);
        }
    }

    float4 bi0 = *(const float4*)&g_bias[col0 + n0];
    float4 bi1 = *(const float4*)&g_bias[col0 + n0 + 4];
    float bn[8] = {bi0.x, bi0.y, bi0.z, bi0.w, bi1.x, bi1.y, bi1.z, bi1.w};
#pragma unroll
    for (int i = 0; i < 8; i++) {
        float v[8];
        upk2(acc[i][0], v[0], v[1]); upk2(acc[i][1], v[2], v[3]);
        upk2(acc[i][2], v[4], v[5]); upk2(acc[i][3], v[6], v[7]);
        float* dst = &g_xg[(size_t)(row0 + m0 + i) * 512 + col0 + n0];
        *(float4*)dst       = make_float4(v[0] + bn[0], v[1] + bn[1], v[2] + bn[2], v[3] + bn[3]);
        *(float4*)(dst + 4) = make_float4(v[4] + bn[4], v[5] + bn[5], v[6] + bn[6], v[7] + bn[7]);
    }
}

// ---------------- persistent LSTM + FC ----------------
#define LS_WS   0                        // 64*128 longlong2 (128 KB): W_hh k in [32q+16,32q+32)
#define LS_XB   (128 * 1024)             // 2*512 float4 (16 KB): xg double buffer
#define LS_PIF  (LS_XB + 16384)          // 16*128 ull (16 KB)
#define LS_PGO  (LS_PIF + 16384)         // 16*128 ull (16 KB)
#define LS_HD   (LS_PGO + 16384)         // 128*4 ull (4 KB): duplicated (h,h) pairs [k][s]
#define LS_TOTAL (LS_HD + 4096)          // 184320 B

__global__ void __launch_bounds__(512, 1) lstm_kernel(
    const float* __restrict__ Wfc, const float* __restrict__ bfc,
    float* __restrict__ out)
{
    extern __shared__ char smem[];
    longlong2* Ws2 = (longlong2*)(smem + LS_WS);
    float4*    xb4 = (float4*)(smem + LS_XB);
    ull*       pIF = (ull*)(smem + LS_PIF);
    ull*       pGO = (ull*)(smem + LS_PGO);
    ull*       hd  = (ull*)(smem + LS_HD);
    const longlong2* hd2 = (const longlong2*)hd;   // [k][{s01,s23}]

    int tid = threadIdx.x;
    int r = tid & 127, q = tid >> 7;
    int s0 = blockIdx.x * 4;

    // register half of W_hh: k in [32q, 32q+16)
    ull WIF[16], WGO[16];
    const longlong2* Wp2 = (const longlong2*)g_Wp;
#pragma unroll
    for (int kk = 0; kk < 16; kk++) {
        longlong2 v = Wp2[(32 * q + kk) * 128 + r];
        WIF[kk] = (ull)v.x; WGO[kk] = (ull)v.y;
    }
    // smem half: k in [32q+16, 32q+32)
    for (int idx = tid; idx < 64 * 128; idx += 512) {
        int kidx = idx >> 7, rr = idx & 127;
        int qq = kidx >> 4, kk = (kidx & 15) + 16;
        Ws2[idx] = Wp2[(32 * qq + kk) * 128 + rr];
    }

    hd[tid < 512 ? tid : 0] = 0ull;
    const float4* xg4 = (const float4*)g_xg;
    xb4[tid] = xg4[(size_t)s0 * 128 + tid];   // t=0 -> buffer 0

    float cst = 0.f;   // c-state for (row r, seq q)
    __syncthreads();

#pragma unroll 1
    for (int t = 0; t < TLEN; t++) {
        float4 nx = make_float4(0.f, 0.f, 0.f, 0.f);
        if (t + 1 < TLEN) nx = xg4[((size_t)(t + 1) * NSEQ + s0) * 128 + tid];

        ull aIF0 = 0, aIF1 = 0, aIF2 = 0, aIF3 = 0;
        ull aGO0 = 0, aGO1 = 0, aGO2 = 0, aGO3 = 0;

#pragma unroll
        for (int kk = 0; kk < 16; kk++) {            // register-W half
            longlong2 hA = hd2[(32 * q + kk) * 2];       // (h,h) for s=0,1
            longlong2 hB = hd2[(32 * q + kk) * 2 + 1];   // (h,h) for s=2,3
            ull h0 = (ull)hA.x, h1 = (ull)hA.y, h2 = (ull)hB.x, h3 = (ull)hB.y;
            fma2(aIF0, WIF[kk], h0); fma2(aGO0, WGO[kk], h0);
            fma2(aIF1, WIF[kk], h1); fma2(aGO1, WGO[kk], h1);
            fma2(aIF2, WIF[kk], h2); fma2(aGO2, WGO[kk], h2);
            fma2(aIF3, WIF[kk], h3); fma2(aGO3, WGO[kk], h3);
        }
#pragma unroll
        for (int kk = 0; kk < 16; kk++) {            // smem-W half
            longlong2 wv = Ws2[(q * 16 + kk) * 128 + r];
            ull wIF = (ull)wv.x, wGO = (ull)wv.y;
            longlong2 hA = hd2[(32 * q + 16 + kk) * 2];
            longlong2 hB = hd2[(32 * q + 16 + kk) * 2 + 1];
            ull h0 = (ull)hA.x, h1 = (ull)hA.y, h2 = (ull)hB.x, h3 = (ull)hB.y;
            fma2(aIF0, wIF, h0); fma2(aGO0, wGO, h0);
            fma2(aIF1, wIF, h1); fma2(aGO1, wGO, h1);
            fma2(aIF2, wIF, h2); fma2(aGO2, wGO, h2);
            fma2(aIF3, wIF, h3); fma2(aGO3, wGO, h3);
        }

        pIF[(q * 4 + 0) * 128 + r] = aIF0;  pGO[(q * 4 + 0) * 128 + r] = aGO0;
        pIF[(q * 4 + 1) * 128 + r] = aIF1;  pGO[(q * 4 + 1) * 128 + r] = aGO1;
        pIF[(q * 4 + 2) * 128 + r] = aIF2;  pGO[(q * 4 + 2) * 128 + r] = aGO2;
        pIF[(q * 4 + 3) * 128 + r] = aIF3;  pGO[(q * 4 + 3) * 128 + r] = aGO3;
        if (t + 1 < TLEN) xb4[((t + 1) & 1) * 512 + tid] = nx;
        __syncthreads();

        // reduce 4 k-quarters + activations; thread owns (r2=r, s2=q)
        int r2 = r, s2 = q;
        ull sIF = pIF[s2 * 128 + r2];
        add2(sIF, pIF[(4 + s2) * 128 + r2]);
        add2(sIF, pIF[(8 + s2) * 128 + r2]);
        add2(sIF, pIF[(12 + s2) * 128 + r2]);
        ull sGO = pGO[s2 * 128 + r2];
        add2(sGO, pGO[(4 + s2) * 128 + r2]);
        add2(sGO, pGO[(8 + s2) * 128 + r2]);
        add2(sGO, pGO[(12 + s2) * 128 + r2]);

        float gi, gf, gg, go;
        upk2(sIF, gi, gf); upk2(sGO, gg, go);
        const float* xb = (const float*)&xb4[(t & 1) * 512];
        gi += xb[s2 * 512 + r2];
        gf += xb[s2 * 512 + 128 + r2];
        gg += xb[s2 * 512 + 256 + r2];
        go += xb[s2 * 512 + 384 + r2];

        float i_ = 0.5f * tanh_t(0.5f * gi) + 0.5f;
        float f_ = 0.5f * tanh_t(0.5f * gf) + 0.5f;
        float o_ = 0.5f * tanh_t(0.5f * go) + 0.5f;
        float g_ = tanh_t(gg);

        cst = f_ * cst + i_ * g_;
        float th = tanh_t(cst);
        float hv = o_ * th;
        hd[r2 * 4 + s2] = pk2(hv, hv);
        __syncthreads();
    }

    // ---- FC epilogue (reuse Ws2 region for transposed W_fc) ----
    float* wfs = (float*)(smem + LS_WS);
    for (int idx = tid; idx < CH * HID; idx += 512) {
        int c = idx >> 7, j = idx & 127;
        wfs[j * 64 + c] = Wfc[idx];
    }
    __syncthreads();
    if (tid < 256) {
        int c = tid & 63, s = tid >> 6;
        float acc = bfc[c];
#pragma unroll 8
        for (int j = 0; j < HID; j++) {
            float hj, dummy;
            upk2(hd[j * 4 + s], hj, dummy);
            acc += hj * wfs[j * 64 + c];
        }
        out[(s0 + s) * 64 + c] = acc;
    }
}

// ---------------- launch ----------------
extern "C" void kernel_launch(void* const* d_in, const int* in_sizes, int n_in,
                              void* d_out, int out_size)
{
    const float* x   = (const float*)d_in[0];
    const float* Wih = (const float*)d_in[1];
    const float* Whh = (const float*)d_in[2];
    const float* bih = (const float*)d_in[3];
    const float* bhh = (const float*)d_in[4];
    const float* Wfc = (const float*)d_in[5];
    const float* bfc = (const float*)d_in[6];
    float* out = (float*)d_out;

    cudaFuncSetAttribute(gemm_kernel, cudaFuncAttributeMaxDynamicSharedMemorySize, GEMM_SMEM);
    cudaFuncSetAttribute(lstm_kernel, cudaFuncAttributeMaxDynamicSharedMemorySize, LS_TOTAL);

    prep_kernel<<<256, 256>>>(Wih, Whh, bih, bhh);
    transp_kernel<<<dim3(TLEN, 16), 256>>>(x);
    gemm_kernel<<<dim3(NROW / 128, G4 / 128), 256, GEMM_SMEM>>>();
    lstm_kernel<<<120, 512, LS_TOTAL>>>(Wfc, bfc, out);
}